// round 2
// baseline (speedup 1.0000x reference)
#include <cuda_runtime.h>
#include <cstdint>

#define S_SEG 8
#define U_CH 128
#define SU 1024            // S_SEG * U_CH
#define P_MAX 64
#define ZPB 8              // z per block
#define WPZ 2              // warps per z
#define NTHREADS (ZPB * WPZ * 32)   // 512

// Preprocessed path metadata (written by prep kernel each launch)
__device__ uint4 g_meta[P_MAX];   // {off0_bytes, off1_bytes, off2_bytes, coeff_bits} sorted by i3
__device__ int   g_start[S_SEG + 1];

__global__ void prep_kernel(const int* __restrict__ path_indices,
                            const float* __restrict__ path_coeff,
                            int P) {
    if (threadIdx.x != 0 || blockIdx.x != 0) return;
    int cnt[S_SEG];
    for (int j = 0; j < S_SEG; j++) cnt[j] = 0;
    for (int p = 0; p < P; p++) cnt[path_indices[p * 4 + 3]]++;
    int st[S_SEG + 1];
    st[0] = 0;
    for (int j = 0; j < S_SEG; j++) st[j + 1] = st[j] + cnt[j];
    for (int j = 0; j <= S_SEG; j++) g_start[j] = st[j];
    int pos[S_SEG];
    for (int j = 0; j < S_SEG; j++) pos[j] = st[j];
    for (int p = 0; p < P; p++) {
        int i0 = path_indices[p * 4 + 0];
        int i1 = path_indices[p * 4 + 1];
        int i2 = path_indices[p * 4 + 2];
        int i3 = path_indices[p * 4 + 3];
        uint4 m;
        // byte offsets into the per-z shared tile: [src*8 + seg] * 128 floats * 4B
        m.x = (unsigned)((0 * S_SEG + i0) * U_CH * 4);
        m.y = (unsigned)((1 * S_SEG + i1) * U_CH * 4);
        m.z = (unsigned)((2 * S_SEG + i2) * U_CH * 4);
        m.w = __float_as_uint(path_coeff[p]);
        g_meta[pos[i3]++] = m;
    }
}

__device__ __forceinline__ unsigned smem_u32(const void* p) {
    unsigned a;
    asm("{ .reg .u64 t; cvta.to.shared.u64 t, %1; cvt.u32.u64 %0, t; }"
        : "=r"(a) : "l"(p));
    return a;
}

__device__ __forceinline__ unsigned long long lds64(unsigned addr) {
    unsigned long long v;
    asm volatile("ld.shared.b64 %0, [%1];" : "=l"(v) : "r"(addr));
    return v;
}

__device__ __forceinline__ unsigned long long mul2(unsigned long long a, unsigned long long b) {
    unsigned long long r;
    asm("mul.rn.f32x2 %0, %1, %2;" : "=l"(r) : "l"(a), "l"(b));
    return r;
}

__device__ __forceinline__ unsigned long long fma2(unsigned long long a, unsigned long long b,
                                                   unsigned long long c) {
    unsigned long long r;
    asm("fma.rn.f32x2 %0, %1, %2, %3;" : "=l"(r) : "l"(a), "l"(b), "l"(c));
    return r;
}

__global__ __launch_bounds__(NTHREADS, 2)
void ftp4_kernel(const float* __restrict__ x0,
                 const float* __restrict__ x1,
                 const float* __restrict__ x2,
                 float* __restrict__ out,
                 int Z) {
    extern __shared__ float smem[];
    // layout: [ZPB][3*S_SEG][U_CH] floats, then meta (64 x uint4), then starts (9 ints)
    uint4* smeta = (uint4*)(smem + ZPB * 3 * S_SEG * U_CH);
    int*   sstart = (int*)(smeta + P_MAX);

    const int tid = threadIdx.x;
    if (tid < P_MAX) smeta[tid] = g_meta[tid];
    if (tid < S_SEG + 1) sstart[tid] = g_start[tid];

    const int ws = tid >> 5;          // warp slot 0..15
    const int zl = ws >> 1;           // z_local 0..7
    const int half = ws & 1;          // u-half 0/1
    const int lane = tid & 31;
    const long z = (long)blockIdx.x * ZPB + zl;
    const bool active = (z < Z);

    float* sz = smem + zl * (3 * S_SEG * U_CH);

    // Cooperative staging: 64 threads (warp pair) copy 3*1024 contiguous floats
    // per source into the tile (tile layout == source layout: [src][seg][u]).
    if (active) {
        const int pt = tid & 63;                  // 0..63 within warp pair
        float4* s4 = (float4*)sz;
        const float4* p0 = (const float4*)(x0 + z * SU);
        const float4* p1 = (const float4*)(x1 + z * SU);
        const float4* p2 = (const float4*)(x2 + z * SU);
#pragma unroll
        for (int c = 0; c < 4; c++) s4[0 * 256 + c * 64 + pt] = p0[c * 64 + pt];
#pragma unroll
        for (int c = 0; c < 4; c++) s4[1 * 256 + c * 64 + pt] = p1[c * 64 + pt];
#pragma unroll
        for (int c = 0; c < 4; c++) s4[2 * 256 + c * 64 + pt] = p2[c * 64 + pt];
    }
    __syncthreads();

    if (!active) return;

    // This warp owns u channels [half*64, half*64+64); lane owns 2 channels.
    const unsigned sbase = smem_u32(sz) + half * 256 + lane * 8;

#pragma unroll
    for (int j = 0; j < S_SEG; j++) {
        unsigned long long acc = 0ull;
        const int pb = sstart[j];
        const int pe = sstart[j + 1];
#pragma unroll 2
        for (int p = pb; p < pe; ++p) {
            uint4 m = smeta[p];
            unsigned long long a = lds64(sbase + m.x);
            unsigned long long b = lds64(sbase + m.y);
            unsigned long long c = lds64(sbase + m.z);
            unsigned long long cc;
            asm("mov.b64 %0, {%1, %1};" : "=l"(cc) : "r"(m.w));
            unsigned long long t = mul2(a, b);
            t = mul2(t, c);
            acc = fma2(t, cc, acc);
        }
        unsigned r0, r1;
        asm("mov.b64 {%0, %1}, %2;" : "=r"(r0), "=r"(r1) : "l"(acc));
        float2 r;
        r.x = __uint_as_float(r0);
        r.y = __uint_as_float(r1);
        *(float2*)(out + z * SU + j * U_CH + half * 64 + lane * 2) = r;
    }
}

extern "C" void kernel_launch(void* const* d_in, const int* in_sizes, int n_in,
                              void* d_out, int out_size) {
    const float* x0 = (const float*)d_in[0];
    const float* x1 = (const float*)d_in[1];
    const float* x2 = (const float*)d_in[2];
    const float* coeff = (const float*)d_in[3];
    const int*   pidx = (const int*)d_in[4];
    float* out = (float*)d_out;

    const int P = in_sizes[3];            // 64
    const int Z = in_sizes[0] / SU;       // 20000

    prep_kernel<<<1, 32>>>(pidx, coeff, P);

    const size_t smem_bytes =
        (size_t)ZPB * 3 * S_SEG * U_CH * sizeof(float) +
        P_MAX * sizeof(uint4) + (S_SEG + 1) * sizeof(int);

    static bool attr_set = false;
    if (!attr_set) {
        cudaFuncSetAttribute(ftp4_kernel,
                             cudaFuncAttributeMaxDynamicSharedMemorySize,
                             (int)smem_bytes);
        attr_set = true;
    }

    const int grid = (Z + ZPB - 1) / ZPB;
    ftp4_kernel<<<grid, NTHREADS, smem_bytes>>>(x0, x1, x2, out, Z);
}

// round 3
// speedup vs baseline: 1.3180x; 1.3180x over previous
#include <cuda_runtime.h>
#include <cstdint>

#define S_SEG 8
#define U_CH 128
#define SU 1024            // S_SEG * U_CH
#define P_MAX 64
#define ZPB 8              // z per block
#define WPZ 2              // warps per z
#define NTHREADS (ZPB * WPZ * 32)   // 512

// Prep output (device staging), then copied into __constant__ each launch.
__device__ uint4 g_meta[P_MAX];   // {off0_bytes, off1_bytes, off2_bytes, coeff_bits}, sorted by i3
__device__ int   g_start[S_SEG + 1];

__constant__ uint4 c_meta[P_MAX];
__constant__ int   c_start[S_SEG + 1];

__global__ void prep_kernel(const int* __restrict__ path_indices,
                            const float* __restrict__ path_coeff,
                            int P) {
    if (threadIdx.x != 0 || blockIdx.x != 0) return;
    int cnt[S_SEG];
    for (int j = 0; j < S_SEG; j++) cnt[j] = 0;
    for (int p = 0; p < P; p++) cnt[path_indices[p * 4 + 3]]++;
    int st[S_SEG + 1];
    st[0] = 0;
    for (int j = 0; j < S_SEG; j++) st[j + 1] = st[j] + cnt[j];
    for (int j = 0; j <= S_SEG; j++) g_start[j] = st[j];
    int pos[S_SEG];
    for (int j = 0; j < S_SEG; j++) pos[j] = st[j];
    for (int p = 0; p < P; p++) {
        int i0 = path_indices[p * 4 + 0];
        int i1 = path_indices[p * 4 + 1];
        int i2 = path_indices[p * 4 + 2];
        int i3 = path_indices[p * 4 + 3];
        uint4 m;
        m.x = (unsigned)((0 * S_SEG + i0) * U_CH * 4);
        m.y = (unsigned)((1 * S_SEG + i1) * U_CH * 4);
        m.z = (unsigned)((2 * S_SEG + i2) * U_CH * 4);
        m.w = __float_as_uint(path_coeff[p]);
        g_meta[pos[i3]++] = m;
    }
}

__device__ __forceinline__ unsigned smem_u32(const void* p) {
    unsigned a;
    asm("{ .reg .u64 t; cvta.to.shared.u64 t, %1; cvt.u32.u64 %0, t; }"
        : "=r"(a) : "l"(p));
    return a;
}

__device__ __forceinline__ unsigned long long lds64(unsigned addr) {
    unsigned long long v;
    asm volatile("ld.shared.b64 %0, [%1];" : "=l"(v) : "r"(addr));
    return v;
}

__device__ __forceinline__ unsigned long long mul2(unsigned long long a, unsigned long long b) {
    unsigned long long r;
    asm("mul.rn.f32x2 %0, %1, %2;" : "=l"(r) : "l"(a), "l"(b));
    return r;
}

__device__ __forceinline__ unsigned long long fma2(unsigned long long a, unsigned long long b,
                                                   unsigned long long c) {
    unsigned long long r;
    asm("fma.rn.f32x2 %0, %1, %2, %3;" : "=l"(r) : "l"(a), "l"(b), "l"(c));
    return r;
}

__device__ __forceinline__ unsigned long long add2(unsigned long long a, unsigned long long b) {
    unsigned long long r;
    asm("add.rn.f32x2 %0, %1, %2;" : "=l"(r) : "l"(a), "l"(b));
    return r;
}

// One path's contribution into acc.
__device__ __forceinline__ void do_path(unsigned long long& acc, unsigned sbase, uint4 m) {
    unsigned long long a = lds64(sbase + m.x);
    unsigned long long b = lds64(sbase + m.y);
    unsigned long long c = lds64(sbase + m.z);
    unsigned long long cc;
    asm("mov.b64 %0, {%1, %1};" : "=l"(cc) : "r"(m.w));
    unsigned long long t = mul2(a, b);
    t = mul2(t, c);
    acc = fma2(t, cc, acc);
}

__global__ __launch_bounds__(NTHREADS, 2)
void ftp4_kernel(const float* __restrict__ x0,
                 const float* __restrict__ x1,
                 const float* __restrict__ x2,
                 float* __restrict__ out,
                 int Z) {
    extern __shared__ float smem[];   // [ZPB][3*S_SEG][U_CH] floats only

    const int tid = threadIdx.x;
    const int ws = tid >> 5;          // warp slot 0..15
    const int zl = ws >> 1;           // z_local 0..7
    const int half = ws & 1;          // u-half 0/1
    const int lane = tid & 31;
    const long z = (long)blockIdx.x * ZPB + zl;
    const bool active = (z < Z);

    float* sz = smem + zl * (3 * S_SEG * U_CH);

    // Cooperative staging: 64 threads (warp pair) copy 3*1024 contiguous floats per z.
    if (active) {
        const int pt = tid & 63;
        float4* s4 = (float4*)sz;
        const float4* p0 = (const float4*)(x0 + z * SU);
        const float4* p1 = (const float4*)(x1 + z * SU);
        const float4* p2 = (const float4*)(x2 + z * SU);
#pragma unroll
        for (int c = 0; c < 4; c++) s4[0 * 256 + c * 64 + pt] = p0[c * 64 + pt];
#pragma unroll
        for (int c = 0; c < 4; c++) s4[1 * 256 + c * 64 + pt] = p1[c * 64 + pt];
#pragma unroll
        for (int c = 0; c < 4; c++) s4[2 * 256 + c * 64 + pt] = p2[c * 64 + pt];
    }
    __syncthreads();

    if (!active) return;

    // This warp owns u channels [half*64, half*64+64); lane owns 2 channels.
    const unsigned sbase = smem_u32(sz) + half * 256 + lane * 8;

#pragma unroll
    for (int j = 0; j < S_SEG; j++) {
        const int pb = c_start[j];
        const int pe = c_start[j + 1];
        unsigned long long acc0 = 0ull, acc1 = 0ull;
        int p = pb;
        for (; p + 1 < pe; p += 2) {
            do_path(acc0, sbase, c_meta[p]);
            do_path(acc1, sbase, c_meta[p + 1]);
        }
        if (p < pe) do_path(acc0, sbase, c_meta[p]);
        unsigned long long acc = add2(acc0, acc1);

        unsigned r0, r1;
        asm("mov.b64 {%0, %1}, %2;" : "=r"(r0), "=r"(r1) : "l"(acc));
        float2 r;
        r.x = __uint_as_float(r0);
        r.y = __uint_as_float(r1);
        *(float2*)(out + z * SU + j * U_CH + half * 64 + lane * 2) = r;
    }
}

extern "C" void kernel_launch(void* const* d_in, const int* in_sizes, int n_in,
                              void* d_out, int out_size) {
    const float* x0 = (const float*)d_in[0];
    const float* x1 = (const float*)d_in[1];
    const float* x2 = (const float*)d_in[2];
    const float* coeff = (const float*)d_in[3];
    const int*   pidx = (const int*)d_in[4];
    float* out = (float*)d_out;

    const int P = in_sizes[3];            // 64
    const int Z = in_sizes[0] / SU;       // 20000

    prep_kernel<<<1, 32>>>(pidx, coeff, P);

    // Device-to-device async copies into constant memory (graph-capturable).
    void* g_meta_addr = nullptr;
    void* g_start_addr = nullptr;
    cudaGetSymbolAddress(&g_meta_addr, g_meta);
    cudaGetSymbolAddress(&g_start_addr, g_start);
    cudaMemcpyToSymbolAsync(c_meta, g_meta_addr, sizeof(uint4) * P_MAX, 0,
                            cudaMemcpyDeviceToDevice, 0);
    cudaMemcpyToSymbolAsync(c_start, g_start_addr, sizeof(int) * (S_SEG + 1), 0,
                            cudaMemcpyDeviceToDevice, 0);

    const size_t smem_bytes = (size_t)ZPB * 3 * S_SEG * U_CH * sizeof(float);

    static bool attr_set = false;
    if (!attr_set) {
        cudaFuncSetAttribute(ftp4_kernel,
                             cudaFuncAttributeMaxDynamicSharedMemorySize,
                             (int)smem_bytes);
        attr_set = true;
    }

    const int grid = (Z + ZPB - 1) / ZPB;
    ftp4_kernel<<<grid, NTHREADS, smem_bytes>>>(x0, x1, x2, out, Z);
}

// round 4
// speedup vs baseline: 1.3379x; 1.0151x over previous
#include <cuda_runtime.h>
#include <cstdint>

#define S_SEG 8
#define U_CH 128
#define SU 1024                 // S_SEG * U_CH
#define P_MAX 64
#define GROUPS 4                // z-streams per block
#define NTHREADS 512            // GROUPS * 4 warps * 32
#define TILE_FLOATS (3 * S_SEG * U_CH)   // 3072 floats = 12 KB
#define GRID_BLOCKS 296         // 2 per SM (148 SMs)

// Prep output (device staging), then copied into __constant__ each launch.
__device__ uint4 g_meta[P_MAX];   // {off0_bytes, off1_bytes, off2_bytes, coeff_bits}, sorted by i3
__device__ int   g_start[S_SEG + 1];

__constant__ uint4 c_meta[P_MAX];
__constant__ int   c_start[S_SEG + 1];

__global__ void prep_kernel(const int* __restrict__ path_indices,
                            const float* __restrict__ path_coeff,
                            int P) {
    if (threadIdx.x != 0 || blockIdx.x != 0) return;
    int cnt[S_SEG];
    for (int j = 0; j < S_SEG; j++) cnt[j] = 0;
    for (int p = 0; p < P; p++) cnt[path_indices[p * 4 + 3]]++;
    int st[S_SEG + 1];
    st[0] = 0;
    for (int j = 0; j < S_SEG; j++) st[j + 1] = st[j] + cnt[j];
    for (int j = 0; j <= S_SEG; j++) g_start[j] = st[j];
    int pos[S_SEG];
    for (int j = 0; j < S_SEG; j++) pos[j] = st[j];
    for (int p = 0; p < P; p++) {
        int i0 = path_indices[p * 4 + 0];
        int i1 = path_indices[p * 4 + 1];
        int i2 = path_indices[p * 4 + 2];
        int i3 = path_indices[p * 4 + 3];
        uint4 m;
        // byte offsets of 512-B rows in the per-z tile: [src][seg][128 floats]
        m.x = (unsigned)((0 * S_SEG + i0) * U_CH * 4);
        m.y = (unsigned)((1 * S_SEG + i1) * U_CH * 4);
        m.z = (unsigned)((2 * S_SEG + i2) * U_CH * 4);
        m.w = __float_as_uint(path_coeff[p]);
        g_meta[pos[i3]++] = m;
    }
}

__device__ __forceinline__ unsigned smem_u32(const void* p) {
    unsigned a;
    asm("{ .reg .u64 t; cvta.to.shared.u64 t, %1; cvt.u32.u64 %0, t; }"
        : "=r"(a) : "l"(p));
    return a;
}

__device__ __forceinline__ float lds32(unsigned addr) {
    float v;
    asm volatile("ld.shared.f32 %0, [%1];" : "=f"(v) : "r"(addr));
    return v;
}

__device__ __forceinline__ void cp16(unsigned saddr, const void* gaddr) {
    asm volatile("cp.async.cg.shared.global [%0], [%1], 16;" :: "r"(saddr), "l"(gaddr));
}

__device__ __forceinline__ void cp_commit() {
    asm volatile("cp.async.commit_group;" ::: "memory");
}

template <int N>
__device__ __forceinline__ void cp_wait() {
    asm volatile("cp.async.wait_group %0;" :: "n"(N) : "memory");
}

__device__ __forceinline__ void group_bar(int gid) {
    asm volatile("bar.sync %0, %1;" :: "r"(gid + 1), "r"(128) : "memory");
}

// Stage one z-tile (12 KB) into shared via cp.async. 128 threads, 6 x 16B each.
// Source per unrolled iteration is compile-time: its {0,1}->x0, {2,3}->x1, {4,5}->x2.
__device__ __forceinline__ void issue_stage(unsigned sdst, long z,
                                            int gt,
                                            const float* __restrict__ x0,
                                            const float* __restrict__ x1,
                                            const float* __restrict__ x2) {
    const float* srcs[3] = {x0, x1, x2};
#pragma unroll
    for (int it = 0; it < 6; it++) {
        const int f = it * 128 + gt;          // 0..767 chunk index (16 B each)
        const int row = f >> 5;               // 0..23 (512-B rows)
        const int col = f & 31;               // 16-B column within row
        const float* gp = srcs[it >> 1] + z * SU + (row & 7) * U_CH + col * 4;
        cp16(sdst + (unsigned)f * 16, gp);
    }
}

__device__ __forceinline__ void do_path(float& acc, unsigned sbase, uint4 m) {
    float a = lds32(sbase + m.x);
    float b = lds32(sbase + m.y);
    float c = lds32(sbase + m.z);
    float t = a * b;
    t = t * c;
    acc = fmaf(t, __uint_as_float(m.w), acc);
}

__global__ __launch_bounds__(NTHREADS, 2)
void ftp4_kernel(const float* __restrict__ x0,
                 const float* __restrict__ x1,
                 const float* __restrict__ x2,
                 float* __restrict__ out,
                 int Z) {
    extern __shared__ float smem[];   // [GROUPS][2][TILE_FLOATS]

    const int tid = threadIdx.x;
    const int ws = tid >> 5;          // warp slot 0..15
    const int g = ws >> 2;            // group (z-stream) 0..3
    const int wq = ws & 3;            // u-quarter 0..3
    const int lane = tid & 31;
    const int gt = tid & 127;         // thread within group

    float* buf0 = smem + g * (2 * TILE_FLOATS);
    float* buf1 = buf0 + TILE_FLOATS;
    const unsigned sb0 = smem_u32(buf0);
    const unsigned sb1 = smem_u32(buf1);

    const int stream = blockIdx.x * GROUPS + g;
    const int stride = GRID_BLOCKS * GROUPS;            // 1184
    const int nz = (Z > stream) ? ((Z - 1 - stream) / stride + 1) : 0;
    if (nz == 0) return;

    // Prologue: stage 0 into buf0
    issue_stage(sb0, (long)stream, gt, x0, x1, x2);
    cp_commit();

    for (int k = 0; k < nz; k++) {
        const long z = (long)stream + (long)k * stride;
        const unsigned scur = (k & 1) ? sb1 : sb0;
        const unsigned snxt = (k & 1) ? sb0 : sb1;

        if (k + 1 < nz) {
            issue_stage(snxt, z + stride, gt, x0, x1, x2);
            cp_commit();
            cp_wait<1>();
        } else {
            cp_wait<0>();
        }
        group_bar(g);   // stage k visible to all 4 warps

        const unsigned sbase = scur + (unsigned)(wq * 128 + lane * 4);
        float* oz = out + z * SU + wq * 32 + lane;

#pragma unroll
        for (int j = 0; j < S_SEG; j++) {
            const int pb = c_start[j];
            const int pe = c_start[j + 1];
            float acc0 = 0.f, acc1 = 0.f;
            int p = pb;
            for (; p + 1 < pe; p += 2) {
                do_path(acc0, sbase, c_meta[p]);
                do_path(acc1, sbase, c_meta[p + 1]);
            }
            if (p < pe) do_path(acc0, sbase, c_meta[p]);
            oz[j * U_CH] = acc0 + acc1;
        }

        group_bar(g);   // all readers done before this buffer is re-staged
    }
}

extern "C" void kernel_launch(void* const* d_in, const int* in_sizes, int n_in,
                              void* d_out, int out_size) {
    const float* x0 = (const float*)d_in[0];
    const float* x1 = (const float*)d_in[1];
    const float* x2 = (const float*)d_in[2];
    const float* coeff = (const float*)d_in[3];
    const int*   pidx = (const int*)d_in[4];
    float* out = (float*)d_out;

    const int P = in_sizes[3];            // 64
    const int Z = in_sizes[0] / SU;       // 20000

    prep_kernel<<<1, 32>>>(pidx, coeff, P);

    void* g_meta_addr = nullptr;
    void* g_start_addr = nullptr;
    cudaGetSymbolAddress(&g_meta_addr, g_meta);
    cudaGetSymbolAddress(&g_start_addr, g_start);
    cudaMemcpyToSymbolAsync(c_meta, g_meta_addr, sizeof(uint4) * P_MAX, 0,
                            cudaMemcpyDeviceToDevice, 0);
    cudaMemcpyToSymbolAsync(c_start, g_start_addr, sizeof(int) * (S_SEG + 1), 0,
                            cudaMemcpyDeviceToDevice, 0);

    const size_t smem_bytes = (size_t)GROUPS * 2 * TILE_FLOATS * sizeof(float); // 96 KB

    static bool attr_set = false;
    if (!attr_set) {
        cudaFuncSetAttribute(ftp4_kernel,
                             cudaFuncAttributeMaxDynamicSharedMemorySize,
                             (int)smem_bytes);
        attr_set = true;
    }

    ftp4_kernel<<<GRID_BLOCKS, NTHREADS, smem_bytes>>>(x0, x1, x2, out, Z);
}